// round 4
// baseline (speedup 1.0000x reference)
#include <cuda_runtime.h>
#include <cstdint>

#define FULL_MASK 0xffffffffu

// Problem constants (hardcoded per reference)
// B=4, N=2048, DIM=1024, H=16, d=64
static constexpr int SEQ = 2048;
static constexpr int DIMC = 1024;

// Scratch for projected Q/K/V in head-split layout [B,H,N,64], fp32.
__device__ float g_Q[4 * 2048 * 1024];
__device__ float g_K[4 * 2048 * 1024];
__device__ float g_V[4 * 2048 * 1024];

static __device__ __forceinline__ float to_tf32(float x) {
    uint32_t u;
    asm("cvt.rna.tf32.f32 %0, %1;" : "=r"(u) : "f"(x));
    return __uint_as_float(u);
}
static __device__ __forceinline__ uint32_t fbits(float x) { return __float_as_uint(x); }

static __device__ __forceinline__ void mma_tf32(float c[4], const uint32_t a[4],
                                                uint32_t b0, uint32_t b1) {
    asm("mma.sync.aligned.m16n8k8.row.col.f32.tf32.tf32.f32 "
        "{%0,%1,%2,%3},{%4,%5,%6,%7},{%8,%9},{%0,%1,%2,%3};"
        : "+f"(c[0]), "+f"(c[1]), "+f"(c[2]), "+f"(c[3])
        : "r"(a[0]), "r"(a[1]), "r"(a[2]), "r"(a[3]), "r"(b0), "r"(b1));
}

// C[m][n] = sum_k A[m][k] * W[n][k]; output written head-split:
// Out[((b*16 + h)*2048 + n)*64 + j] with b=m/2048, n=m%2048, h=nn/64, j=nn%64.
__global__ void __launch_bounds__(256) proj_gemm(const float* __restrict__ A,
                                                 const float* __restrict__ W,
                                                 float* __restrict__ Out) {
    __shared__ float As[128][36];
    __shared__ float Bs[128][36];
    const int tid = threadIdx.x;
    const int lane = tid & 31;
    const int warp = tid >> 5;
    const int wm = warp & 1;      // 2 warps along M
    const int wn = warp >> 1;     // 4 warps along N
    const int mBase = blockIdx.y * 128;
    const int nBase = blockIdx.x * 128;

    float c[4][4][4];
#pragma unroll
    for (int i = 0; i < 4; i++)
#pragma unroll
        for (int j = 0; j < 4; j++)
#pragma unroll
            for (int k = 0; k < 4; k++) c[i][j][k] = 0.f;

    const int ldRow = tid >> 3;          // 0..31
    const int ldCol = (tid & 7) << 2;    // 0..28

    for (int k0 = 0; k0 < DIMC; k0 += 32) {
        float4 ra[4], rb[4];
#pragma unroll
        for (int p = 0; p < 4; p++) {
            ra[p] = *(const float4*)&A[(size_t)(mBase + ldRow + 32 * p) * DIMC + k0 + ldCol];
            rb[p] = *(const float4*)&W[(size_t)(nBase + ldRow + 32 * p) * DIMC + k0 + ldCol];
        }
        __syncthreads();
#pragma unroll
        for (int p = 0; p < 4; p++) {
            float4 ta;
            ta.x = to_tf32(ra[p].x); ta.y = to_tf32(ra[p].y);
            ta.z = to_tf32(ra[p].z); ta.w = to_tf32(ra[p].w);
            *(float4*)&As[ldRow + 32 * p][ldCol] = ta;
            float4 tb;
            tb.x = to_tf32(rb[p].x); tb.y = to_tf32(rb[p].y);
            tb.z = to_tf32(rb[p].z); tb.w = to_tf32(rb[p].w);
            *(float4*)&Bs[ldRow + 32 * p][ldCol] = tb;
        }
        __syncthreads();

#pragma unroll
        for (int kk = 0; kk < 32; kk += 8) {
            uint32_t a[4][4];
#pragma unroll
            for (int mi = 0; mi < 4; mi++) {
                const int r = wm * 64 + mi * 16 + (lane >> 2);
                const int col = kk + (lane & 3);
                a[mi][0] = fbits(As[r][col]);
                a[mi][1] = fbits(As[r + 8][col]);
                a[mi][2] = fbits(As[r][col + 4]);
                a[mi][3] = fbits(As[r + 8][col + 4]);
            }
#pragma unroll
            for (int nf = 0; nf < 4; nf++) {
                const int n = wn * 32 + nf * 8 + (lane >> 2);
                const int col = kk + (lane & 3);
                const uint32_t b0 = fbits(Bs[n][col]);
                const uint32_t b1 = fbits(Bs[n][col + 4]);
#pragma unroll
                for (int mi = 0; mi < 4; mi++) mma_tf32(c[mi][nf], a[mi], b0, b1);
            }
        }
    }

#pragma unroll
    for (int mi = 0; mi < 4; mi++) {
        const int gm = mBase + wm * 64 + mi * 16 + (lane >> 2);
        const int b = gm >> 11;
        const int n = gm & 2047;
#pragma unroll
        for (int nf = 0; nf < 4; nf++) {
            const int gn = nBase + wn * 32 + nf * 8 + ((lane & 3) << 1);
            const int h = gn >> 6;
            const int j = gn & 63;
            const size_t base = (((size_t)(b * 16 + h) * SEQ) + n) * 64 + j;
            *(float2*)&Out[base] = make_float2(c[mi][nf][0], c[mi][nf][1]);
            *(float2*)&Out[base + 8 * 64] = make_float2(c[mi][nf][2], c[mi][nf][3]);
        }
    }
}

// Flash attention: one CTA = 64 query rows for one (b,h); KV tile = 32.
__global__ void __launch_bounds__(128) attn(const float* __restrict__ Q,
                                            const float* __restrict__ K,
                                            const float* __restrict__ V,
                                            float* __restrict__ Out) {
    __shared__ float Qs[64][68];
    __shared__ float Ks[32][68];
    __shared__ float Vs[32][72];
    const int tid = threadIdx.x;
    const int lane = tid & 31;
    const int warp = tid >> 5;
    const int bh = blockIdx.y;          // b*16 + h
    const int qBase = blockIdx.x * 64;
    const float* Qg = Q + (size_t)bh * SEQ * 64;
    const float* Kg = K + (size_t)bh * SEQ * 64;
    const float* Vg = V + (size_t)bh * SEQ * 64;

    // Q tile -> smem (tf32-rounded)
    {
        const int r = tid >> 4;              // 0..7
        const int cc = (tid & 15) << 2;      // 0..60
#pragma unroll
        for (int p = 0; p < 8; p++) {
            float4 v = *(const float4*)&Qg[(size_t)(qBase + r + 8 * p) * 64 + cc];
            float4 t;
            t.x = to_tf32(v.x); t.y = to_tf32(v.y); t.z = to_tf32(v.z); t.w = to_tf32(v.w);
            *(float4*)&Qs[r + 8 * p][cc] = t;
        }
    }

    float m0 = -1e30f, m1 = -1e30f, l0 = 0.f, l1 = 0.f;
    float o[8][4];
#pragma unroll
    for (int nf = 0; nf < 8; nf++)
#pragma unroll
        for (int k = 0; k < 4; k++) o[nf][k] = 0.f;

    const int ldr = tid >> 4;            // 0..7
    const int ldc = (tid & 15) << 2;     // 0..60
    const int srcLo = (lane & ~3) + ((lane & 3) >> 1);
    const int srcHi = srcLo + 2;
    const bool odd = lane & 1;

    for (int t = 0; t < SEQ / 32; t++) {
        const int kvBase = t * 32;
        float4 rk[4], rv[4];
#pragma unroll
        for (int p = 0; p < 4; p++) {
            rk[p] = *(const float4*)&Kg[(size_t)(kvBase + ldr + 8 * p) * 64 + ldc];
            rv[p] = *(const float4*)&Vg[(size_t)(kvBase + ldr + 8 * p) * 64 + ldc];
        }
        __syncthreads();
#pragma unroll
        for (int p = 0; p < 4; p++) {
            float4 tk;
            tk.x = to_tf32(rk[p].x); tk.y = to_tf32(rk[p].y);
            tk.z = to_tf32(rk[p].z); tk.w = to_tf32(rk[p].w);
            *(float4*)&Ks[ldr + 8 * p][ldc] = tk;
            float4 tv;
            tv.x = to_tf32(rv[p].x); tv.y = to_tf32(rv[p].y);
            tv.z = to_tf32(rv[p].z); tv.w = to_tf32(rv[p].w);
            *(float4*)&Vs[ldr + 8 * p][ldc] = tv;
        }
        __syncthreads();

        // S = Q K^T  (16 rows per warp x 32 kv)
        float s[4][4];
#pragma unroll
        for (int nf = 0; nf < 4; nf++)
#pragma unroll
            for (int k = 0; k < 4; k++) s[nf][k] = 0.f;

#pragma unroll
        for (int kk = 0; kk < 64; kk += 8) {
            uint32_t a[4];
            const int r = warp * 16 + (lane >> 2);
            const int col = kk + (lane & 3);
            a[0] = fbits(Qs[r][col]);
            a[1] = fbits(Qs[r + 8][col]);
            a[2] = fbits(Qs[r][col + 4]);
            a[3] = fbits(Qs[r + 8][col + 4]);
#pragma unroll
            for (int nf = 0; nf < 4; nf++) {
                const int n = nf * 8 + (lane >> 2);
                const uint32_t b0 = fbits(Ks[n][col]);
                const uint32_t b1 = fbits(Ks[n][col + 4]);
                mma_tf32(s[nf], a, b0, b1);
            }
        }

        // online softmax (rows r0=warp*16+lane/4, r1=r0+8)
        float tm0 = -1e30f, tm1 = -1e30f;
#pragma unroll
        for (int nf = 0; nf < 4; nf++) {
            s[nf][0] *= 0.125f; s[nf][1] *= 0.125f;
            s[nf][2] *= 0.125f; s[nf][3] *= 0.125f;
            tm0 = fmaxf(tm0, fmaxf(s[nf][0], s[nf][1]));
            tm1 = fmaxf(tm1, fmaxf(s[nf][2], s[nf][3]));
        }
        tm0 = fmaxf(tm0, __shfl_xor_sync(FULL_MASK, tm0, 1));
        tm0 = fmaxf(tm0, __shfl_xor_sync(FULL_MASK, tm0, 2));
        tm1 = fmaxf(tm1, __shfl_xor_sync(FULL_MASK, tm1, 1));
        tm1 = fmaxf(tm1, __shfl_xor_sync(FULL_MASK, tm1, 2));
        const float nm0 = fmaxf(m0, tm0);
        const float nm1 = fmaxf(m1, tm1);
        const float al0 = __expf(m0 - nm0);
        const float al1 = __expf(m1 - nm1);
        float rs0 = 0.f, rs1 = 0.f;
#pragma unroll
        for (int nf = 0; nf < 4; nf++) {
            s[nf][0] = __expf(s[nf][0] - nm0);
            s[nf][1] = __expf(s[nf][1] - nm0);
            s[nf][2] = __expf(s[nf][2] - nm1);
            s[nf][3] = __expf(s[nf][3] - nm1);
            rs0 += s[nf][0] + s[nf][1];
            rs1 += s[nf][2] + s[nf][3];
        }
        rs0 += __shfl_xor_sync(FULL_MASK, rs0, 1);
        rs0 += __shfl_xor_sync(FULL_MASK, rs0, 2);
        rs1 += __shfl_xor_sync(FULL_MASK, rs1, 1);
        rs1 += __shfl_xor_sync(FULL_MASK, rs1, 2);
        l0 = l0 * al0 + rs0;
        l1 = l1 * al1 + rs1;
        m0 = nm0; m1 = nm1;
#pragma unroll
        for (int nf = 0; nf < 8; nf++) {
            o[nf][0] *= al0; o[nf][1] *= al0;
            o[nf][2] *= al1; o[nf][3] *= al1;
        }

        // O += P V : permute C-frag (cols {2c,2c+1}) into A-frag (cols {c, c+4})
#pragma unroll
        for (int kt = 0; kt < 4; kt++) {
            const float v0 = to_tf32(s[kt][0]), v1 = to_tf32(s[kt][1]);
            const float v2 = to_tf32(s[kt][2]), v3 = to_tf32(s[kt][3]);
            const float x0l = __shfl_sync(FULL_MASK, v0, srcLo);
            const float x1l = __shfl_sync(FULL_MASK, v1, srcLo);
            const float x0h = __shfl_sync(FULL_MASK, v0, srcHi);
            const float x1h = __shfl_sync(FULL_MASK, v1, srcHi);
            const float y0l = __shfl_sync(FULL_MASK, v2, srcLo);
            const float y1l = __shfl_sync(FULL_MASK, v3, srcLo);
            const float y0h = __shfl_sync(FULL_MASK, v2, srcHi);
            const float y1h = __shfl_sync(FULL_MASK, v3, srcHi);
            uint32_t a[4];
            a[0] = fbits(odd ? x1l : x0l);
            a[1] = fbits(odd ? y1l : y0l);
            a[2] = fbits(odd ? x1h : x0h);
            a[3] = fbits(odd ? y1h : y0h);
#pragma unroll
            for (int nf = 0; nf < 8; nf++) {
                const int n = nf * 8 + (lane >> 2);
                const uint32_t b0 = fbits(Vs[kt * 8 + (lane & 3)][n]);
                const uint32_t b1 = fbits(Vs[kt * 8 + (lane & 3) + 4][n]);
                mma_tf32(o[nf], a, b0, b1);
            }
        }
    }

    // epilogue: Out[b, q, h*64 + j] = O / l
    const float inv0 = 1.f / l0;
    const float inv1 = 1.f / l1;
    const int b = bh >> 4;
    const int h = bh & 15;
    const int r0 = qBase + warp * 16 + (lane >> 2);
#pragma unroll
    for (int nf = 0; nf < 8; nf++) {
        const int col = h * 64 + nf * 8 + ((lane & 3) << 1);
        const size_t i0 = ((size_t)b * SEQ + r0) * DIMC + col;
        *(float2*)&Out[i0] = make_float2(o[nf][0] * inv0, o[nf][1] * inv0);
        *(float2*)&Out[i0 + (size_t)8 * DIMC] = make_float2(o[nf][2] * inv1, o[nf][3] * inv1);
    }
}

extern "C" void kernel_launch(void* const* d_in, const int* in_sizes, int n_in,
                              void* d_out, int out_size) {
    const float* x  = (const float*)d_in[0];
    const float* kv = (const float*)d_in[1];
    const float* Wq = (const float*)d_in[2];
    const float* Wk = (const float*)d_in[3];
    const float* Wv = (const float*)d_in[4];
    float* out = (float*)d_out;

    float *Qg, *Kg, *Vg;
    cudaGetSymbolAddress((void**)&Qg, g_Q);
    cudaGetSymbolAddress((void**)&Kg, g_K);
    cudaGetSymbolAddress((void**)&Vg, g_V);

    dim3 gg(DIMC / 128, (4 * SEQ) / 128);   // (8, 64)
    proj_gemm<<<gg, 256>>>(x,  Wq, Qg);
    proj_gemm<<<gg, 256>>>(kv, Wk, Kg);
    proj_gemm<<<gg, 256>>>(kv, Wv, Vg);
    attn<<<dim3(SEQ / 64, 64), 128>>>(Qg, Kg, Vg, out);
}

// round 5
// speedup vs baseline: 1.1622x; 1.1622x over previous
#include <cuda_runtime.h>
#include <cstdint>

#define FULL_MASK 0xffffffffu

// Problem constants: B=4, N=2048, DIM=1024, H=16, d=64
static constexpr int SEQ = 2048;
static constexpr int DIMC = 1024;

// Scratch for projected Q/K/V in head-split layout [B,H,N,64].
// Values are tf32-rounded fp32 (Q additionally pre-scaled by 1/8).
__device__ float g_Q[4 * 2048 * 1024];
__device__ float g_K[4 * 2048 * 1024];
__device__ float g_V[4 * 2048 * 1024];

static __device__ __forceinline__ float to_tf32(float x) {
    uint32_t u;
    asm("cvt.rna.tf32.f32 %0, %1;" : "=r"(u) : "f"(x));
    return __uint_as_float(u);
}
static __device__ __forceinline__ uint32_t fbits(float x) { return __float_as_uint(x); }

static __device__ __forceinline__ void mma_tf32(float c[4], const uint32_t a[4],
                                                uint32_t b0, uint32_t b1) {
    asm("mma.sync.aligned.m16n8k8.row.col.f32.tf32.tf32.f32 "
        "{%0,%1,%2,%3},{%4,%5,%6,%7},{%8,%9},{%0,%1,%2,%3};"
        : "+f"(c[0]), "+f"(c[1]), "+f"(c[2]), "+f"(c[3])
        : "r"(a[0]), "r"(a[1]), "r"(a[2]), "r"(a[3]), "r"(b0), "r"(b1));
}

static __device__ __forceinline__ uint32_t smem_u32(const void* p) {
    return (uint32_t)__cvta_generic_to_shared(p);
}
static __device__ __forceinline__ void cp16(uint32_t dst, const void* src) {
    asm volatile("cp.async.cg.shared.global [%0], [%1], 16;" :: "r"(dst), "l"(src));
}
static __device__ __forceinline__ void cp_commit() {
    asm volatile("cp.async.commit_group;");
}
template <int N>
static __device__ __forceinline__ void cp_wait() {
    asm volatile("cp.async.wait_group %0;" :: "n"(N));
}

// C[m][n] = sum_k A[m][k] * W[n][k]; stores to_tf32(C * scale), head-split layout.
__global__ void __launch_bounds__(256) proj_gemm(const float* __restrict__ A,
                                                 const float* __restrict__ W,
                                                 float* __restrict__ Out,
                                                 float scale) {
    __shared__ float As[128][36];
    __shared__ float Bs[128][36];
    const int tid = threadIdx.x;
    const int lane = tid & 31;
    const int warp = tid >> 5;
    const int wm = warp & 1;
    const int wn = warp >> 1;
    const int mBase = blockIdx.y * 128;
    const int nBase = blockIdx.x * 128;

    float c[4][4][4];
#pragma unroll
    for (int i = 0; i < 4; i++)
#pragma unroll
        for (int j = 0; j < 4; j++)
#pragma unroll
            for (int k = 0; k < 4; k++) c[i][j][k] = 0.f;

    const int ldRow = tid >> 3;
    const int ldCol = (tid & 7) << 2;

    for (int k0 = 0; k0 < DIMC; k0 += 32) {
        float4 ra[4], rb[4];
#pragma unroll
        for (int p = 0; p < 4; p++) {
            ra[p] = *(const float4*)&A[(size_t)(mBase + ldRow + 32 * p) * DIMC + k0 + ldCol];
            rb[p] = *(const float4*)&W[(size_t)(nBase + ldRow + 32 * p) * DIMC + k0 + ldCol];
        }
        __syncthreads();
#pragma unroll
        for (int p = 0; p < 4; p++) {
            float4 ta;
            ta.x = to_tf32(ra[p].x); ta.y = to_tf32(ra[p].y);
            ta.z = to_tf32(ra[p].z); ta.w = to_tf32(ra[p].w);
            *(float4*)&As[ldRow + 32 * p][ldCol] = ta;
            float4 tb;
            tb.x = to_tf32(rb[p].x); tb.y = to_tf32(rb[p].y);
            tb.z = to_tf32(rb[p].z); tb.w = to_tf32(rb[p].w);
            *(float4*)&Bs[ldRow + 32 * p][ldCol] = tb;
        }
        __syncthreads();

#pragma unroll
        for (int kk = 0; kk < 32; kk += 8) {
            uint32_t a[4][4];
#pragma unroll
            for (int mi = 0; mi < 4; mi++) {
                const int r = wm * 64 + mi * 16 + (lane >> 2);
                const int col = kk + (lane & 3);
                a[mi][0] = fbits(As[r][col]);
                a[mi][1] = fbits(As[r + 8][col]);
                a[mi][2] = fbits(As[r][col + 4]);
                a[mi][3] = fbits(As[r + 8][col + 4]);
            }
#pragma unroll
            for (int nf = 0; nf < 4; nf++) {
                const int n = wn * 32 + nf * 8 + (lane >> 2);
                const int col = kk + (lane & 3);
                const uint32_t b0 = fbits(Bs[n][col]);
                const uint32_t b1 = fbits(Bs[n][col + 4]);
#pragma unroll
                for (int mi = 0; mi < 4; mi++) mma_tf32(c[mi][nf], a[mi], b0, b1);
            }
        }
    }

#pragma unroll
    for (int mi = 0; mi < 4; mi++) {
        const int gm = mBase + wm * 64 + mi * 16 + (lane >> 2);
        const int b = gm >> 11;
        const int n = gm & 2047;
#pragma unroll
        for (int nf = 0; nf < 4; nf++) {
            const int gn = nBase + wn * 32 + nf * 8 + ((lane & 3) << 1);
            const int h = gn >> 6;
            const int j = gn & 63;
            const size_t base = (((size_t)(b * 16 + h) * SEQ) + n) * 64 + j;
            *(float2*)&Out[base] =
                make_float2(to_tf32(c[mi][nf][0] * scale), to_tf32(c[mi][nf][1] * scale));
            *(float2*)&Out[base + 8 * 64] =
                make_float2(to_tf32(c[mi][nf][2] * scale), to_tf32(c[mi][nf][3] * scale));
        }
    }
}

// Flash attention: CTA = 64 query rows for one (b,h); KV tile = 32,
// cp.async double-buffered K/V, Q fragments register-resident.
__global__ void __launch_bounds__(128, 4) attn(const float* __restrict__ Q,
                                               const float* __restrict__ K,
                                               const float* __restrict__ V,
                                               float* __restrict__ Out) {
    // Layout (floats): Kbuf0[32][68] @0, Kbuf1 @2176, Vbuf0[32][72] @4352, Vbuf1 @6656.
    // Q staging (64x68 = 4352 floats) aliases Kbuf0+Kbuf1 during the prologue.
    __shared__ float sm[2 * 32 * 68 + 2 * 32 * 72];
    float (*Qs)[68] = (float (*)[68])sm;

    const int tid = threadIdx.x;
    const int lane = tid & 31;
    const int warp = tid >> 5;
    const int bh = blockIdx.y;
    const int qBase = blockIdx.x * 64;
    const float* Qg = Q + (size_t)bh * SEQ * 64;
    const float* Kg = K + (size_t)bh * SEQ * 64;
    const float* Vg = V + (size_t)bh * SEQ * 64;

    // --- Prologue: stage Q tile, pull fragments into registers ---
    {
        const int r = tid >> 4;
        const int cc = (tid & 15) << 2;
#pragma unroll
        for (int p = 0; p < 8; p++)
            *(float4*)&Qs[r + 8 * p][cc] =
                *(const float4*)&Qg[(size_t)(qBase + r + 8 * p) * 64 + cc];
    }
    __syncthreads();

    uint32_t qa[8][4];
    {
        const int r = warp * 16 + (lane >> 2);
        const int c0 = lane & 3;
#pragma unroll
        for (int kk = 0; kk < 8; kk++) {
            const int col = kk * 8 + c0;
            qa[kk][0] = fbits(Qs[r][col]);
            qa[kk][1] = fbits(Qs[r + 8][col]);
            qa[kk][2] = fbits(Qs[r][col + 4]);
            qa[kk][3] = fbits(Qs[r + 8][col + 4]);
        }
    }
    __syncthreads();   // Q staging region is about to be overwritten by K buffers

    // cp.async addressing: 512 16B-chunks per K tile, 4 per thread (same for V)
    const int chRow = tid >> 4;            // rows 0..7 (+8 per i)
    const int chCol = (tid & 15) << 2;     // float col 0..60
    const uint32_t kDst0 = smem_u32(&sm[0]) + (uint32_t)(chRow * 68 + chCol) * 4u;
    const uint32_t vDst0 = smem_u32(&sm[4352]) + (uint32_t)(chRow * 72 + chCol) * 4u;

    auto issue_tile = [&](int t) {
        const int buf = t & 1;
        const int kvBase = t * 32;
        const uint32_t kD = kDst0 + buf * (2176 * 4);
        const uint32_t vD = vDst0 + buf * (2304 * 4);
#pragma unroll
        for (int i = 0; i < 4; i++) {
            const int row = chRow + 8 * i;
            cp16(kD + i * (8 * 68 * 4), &Kg[(size_t)(kvBase + row) * 64 + chCol]);
            cp16(vD + i * (8 * 72 * 4), &Vg[(size_t)(kvBase + row) * 64 + chCol]);
        }
        cp_commit();
    };

    constexpr int T = SEQ / 32;
    issue_tile(0);
    issue_tile(1);

    float m0 = -1e30f, m1 = -1e30f, l0 = 0.f, l1 = 0.f;
    float o[8][4];
#pragma unroll
    for (int nf = 0; nf < 8; nf++)
#pragma unroll
        for (int k = 0; k < 4; k++) o[nf][k] = 0.f;

    const int srcLo = (lane & ~3) + ((lane & 3) >> 1);
    const int srcHi = srcLo + 2;
    const bool odd = lane & 1;

    for (int t = 0; t < T; t++) {
        if (t < T - 1) cp_wait<1>(); else cp_wait<0>();
        __syncthreads();

        const int buf = t & 1;
        const float(*Ks)[68] = (const float(*)[68])&sm[buf * 2176];
        const float(*Vs)[72] = (const float(*)[72])&sm[4352 + buf * 2304];

        // S = Q K^T  (Q pre-scaled by 1/8 at projection)
        float s[4][4];
#pragma unroll
        for (int nf = 0; nf < 4; nf++)
#pragma unroll
            for (int k = 0; k < 4; k++) s[nf][k] = 0.f;

#pragma unroll
        for (int kk = 0; kk < 8; kk++) {
            const int col = kk * 8 + (lane & 3);
#pragma unroll
            for (int nf = 0; nf < 4; nf++) {
                const int n = nf * 8 + (lane >> 2);
                const uint32_t b0 = fbits(Ks[n][col]);
                const uint32_t b1 = fbits(Ks[n][col + 4]);
                mma_tf32(s[nf], qa[kk], b0, b1);
            }
        }

        // online softmax (rows r0, r1=r0+8 per lane)
        float tm0 = -1e30f, tm1 = -1e30f;
#pragma unroll
        for (int nf = 0; nf < 4; nf++) {
            tm0 = fmaxf(tm0, fmaxf(s[nf][0], s[nf][1]));
            tm1 = fmaxf(tm1, fmaxf(s[nf][2], s[nf][3]));
        }
        tm0 = fmaxf(tm0, __shfl_xor_sync(FULL_MASK, tm0, 1));
        tm0 = fmaxf(tm0, __shfl_xor_sync(FULL_MASK, tm0, 2));
        tm1 = fmaxf(tm1, __shfl_xor_sync(FULL_MASK, tm1, 1));
        tm1 = fmaxf(tm1, __shfl_xor_sync(FULL_MASK, tm1, 2));
        const float nm0 = fmaxf(m0, tm0);
        const float nm1 = fmaxf(m1, tm1);
        const float al0 = __expf(m0 - nm0);
        const float al1 = __expf(m1 - nm1);
        float rs0 = 0.f, rs1 = 0.f;
#pragma unroll
        for (int nf = 0; nf < 4; nf++) {
            s[nf][0] = __expf(s[nf][0] - nm0);
            s[nf][1] = __expf(s[nf][1] - nm0);
            s[nf][2] = __expf(s[nf][2] - nm1);
            s[nf][3] = __expf(s[nf][3] - nm1);
            rs0 += s[nf][0] + s[nf][1];
            rs1 += s[nf][2] + s[nf][3];
        }
        rs0 += __shfl_xor_sync(FULL_MASK, rs0, 1);
        rs0 += __shfl_xor_sync(FULL_MASK, rs0, 2);
        rs1 += __shfl_xor_sync(FULL_MASK, rs1, 1);
        rs1 += __shfl_xor_sync(FULL_MASK, rs1, 2);
        l0 = l0 * al0 + rs0;
        l1 = l1 * al1 + rs1;
        m0 = nm0; m1 = nm1;
#pragma unroll
        for (int nf = 0; nf < 8; nf++) {
            o[nf][0] *= al0; o[nf][1] *= al0;
            o[nf][2] *= al1; o[nf][3] *= al1;
        }

        // O += P V : permute C-frag cols {2c,2c+1} into A-frag cols {c, c+4}
#pragma unroll
        for (int kt = 0; kt < 4; kt++) {
            const float v0 = to_tf32(s[kt][0]), v1 = to_tf32(s[kt][1]);
            const float v2 = to_tf32(s[kt][2]), v3 = to_tf32(s[kt][3]);
            const float x0l = __shfl_sync(FULL_MASK, v0, srcLo);
            const float x1l = __shfl_sync(FULL_MASK, v1, srcLo);
            const float x0h = __shfl_sync(FULL_MASK, v0, srcHi);
            const float x1h = __shfl_sync(FULL_MASK, v1, srcHi);
            const float y0l = __shfl_sync(FULL_MASK, v2, srcLo);
            const float y1l = __shfl_sync(FULL_MASK, v3, srcLo);
            const float y0h = __shfl_sync(FULL_MASK, v2, srcHi);
            const float y1h = __shfl_sync(FULL_MASK, v3, srcHi);
            uint32_t a[4];
            a[0] = fbits(odd ? x1l : x0l);
            a[1] = fbits(odd ? y1l : y0l);
            a[2] = fbits(odd ? x1h : x0h);
            a[3] = fbits(odd ? y1h : y0h);
#pragma unroll
            for (int nf = 0; nf < 8; nf++) {
                const int n = nf * 8 + (lane >> 2);
                const uint32_t b0 = fbits(Vs[kt * 8 + (lane & 3)][n]);
                const uint32_t b1 = fbits(Vs[kt * 8 + (lane & 3) + 4][n]);
                mma_tf32(o[nf], a, b0, b1);
            }
        }

        __syncthreads();   // all warps done with buf before it is refilled
        if (t + 2 < T) issue_tile(t + 2);
    }

    // epilogue: Out[b, q, h*64 + j] = O / l
    const float inv0 = 1.f / l0;
    const float inv1 = 1.f / l1;
    const int b = bh >> 4;
    const int h = bh & 15;
    const int r0 = qBase + warp * 16 + (lane >> 2);
#pragma unroll
    for (int nf = 0; nf < 8; nf++) {
        const int col = h * 64 + nf * 8 + ((lane & 3) << 1);
        const size_t i0 = ((size_t)b * SEQ + r0) * DIMC + col;
        *(float2*)&Out[i0] = make_float2(o[nf][0] * inv0, o[nf][1] * inv0);
        *(float2*)&Out[i0 + (size_t)8 * DIMC] = make_float2(o[nf][2] * inv1, o[nf][3] * inv1);
    }
}

extern "C" void kernel_launch(void* const* d_in, const int* in_sizes, int n_in,
                              void* d_out, int out_size) {
    const float* x  = (const float*)d_in[0];
    const float* kv = (const float*)d_in[1];
    const float* Wq = (const float*)d_in[2];
    const float* Wk = (const float*)d_in[3];
    const float* Wv = (const float*)d_in[4];
    float* out = (float*)d_out;

    float *Qg, *Kg, *Vg;
    cudaGetSymbolAddress((void**)&Qg, g_Q);
    cudaGetSymbolAddress((void**)&Kg, g_K);
    cudaGetSymbolAddress((void**)&Vg, g_V);

    dim3 gg(DIMC / 128, (4 * SEQ) / 128);   // (8, 64)
    proj_gemm<<<gg, 256>>>(x,  Wq, Qg, 0.125f);  // fold 1/sqrt(64) into Q
    proj_gemm<<<gg, 256>>>(kv, Wk, Kg, 1.0f);
    proj_gemm<<<gg, 256>>>(kv, Wv, Vg, 1.0f);
    attn<<<dim3(SEQ / 64, 64), 128>>>(Qg, Kg, Vg, out);
}

// round 6
// speedup vs baseline: 1.1886x; 1.0226x over previous
#include <cuda_runtime.h>
#include <cstdint>

#define FULL_MASK 0xffffffffu

// Problem constants: B=4, N=2048, DIM=1024, H=16, d=64
static constexpr int SEQ = 2048;
static constexpr int DIMC = 1024;

// Scratch for projected Q/K/V in head-split layout [B,H,N,64].
// Values are tf32-rounded fp32 (Q additionally pre-scaled by 1/8).
__device__ float g_Q[4 * 2048 * 1024];
__device__ float g_K[4 * 2048 * 1024];
__device__ float g_V[4 * 2048 * 1024];

static __device__ __forceinline__ float to_tf32(float x) {
    uint32_t u;
    asm("cvt.rna.tf32.f32 %0, %1;" : "=r"(u) : "f"(x));
    return __uint_as_float(u);
}
static __device__ __forceinline__ uint32_t fbits(float x) { return __float_as_uint(x); }

static __device__ __forceinline__ void mma_tf32(float c[4], const uint32_t a[4],
                                                uint32_t b0, uint32_t b1) {
    asm("mma.sync.aligned.m16n8k8.row.col.f32.tf32.tf32.f32 "
        "{%0,%1,%2,%3},{%4,%5,%6,%7},{%8,%9},{%0,%1,%2,%3};"
        : "+f"(c[0]), "+f"(c[1]), "+f"(c[2]), "+f"(c[3])
        : "r"(a[0]), "r"(a[1]), "r"(a[2]), "r"(a[3]), "r"(b0), "r"(b1));
}

static __device__ __forceinline__ uint32_t smem_u32(const void* p) {
    return (uint32_t)__cvta_generic_to_shared(p);
}
static __device__ __forceinline__ void cp16(uint32_t dst, const void* src) {
    asm volatile("cp.async.cg.shared.global [%0], [%1], 16;" :: "r"(dst), "l"(src));
}
static __device__ __forceinline__ void cp_commit() {
    asm volatile("cp.async.commit_group;");
}
template <int N>
static __device__ __forceinline__ void cp_wait() {
    asm volatile("cp.async.wait_group %0;" :: "n"(N));
}

// C[m][n] = sum_k A[m][k] * W[n][k]; stores to_tf32(C * scale), head-split layout.
// Software-pipelined: next k-slab's LDGs issue before the MMA block.
__global__ void __launch_bounds__(256) proj_gemm(const float* __restrict__ A,
                                                 const float* __restrict__ W,
                                                 float* __restrict__ Out,
                                                 float scale) {
    __shared__ float As[128][36];
    __shared__ float Bs[128][36];
    const int tid = threadIdx.x;
    const int lane = tid & 31;
    const int warp = tid >> 5;
    const int wm = warp & 1;
    const int wn = warp >> 1;
    const int mBase = blockIdx.y * 128;
    const int nBase = blockIdx.x * 128;

    float c[4][4][4];
#pragma unroll
    for (int i = 0; i < 4; i++)
#pragma unroll
        for (int j = 0; j < 4; j++)
#pragma unroll
            for (int k = 0; k < 4; k++) c[i][j][k] = 0.f;

    const int ldRow = tid >> 3;
    const int ldCol = (tid & 7) << 2;

    float4 ra[4], rb[4];
#pragma unroll
    for (int p = 0; p < 4; p++) {
        ra[p] = *(const float4*)&A[(size_t)(mBase + ldRow + 32 * p) * DIMC + ldCol];
        rb[p] = *(const float4*)&W[(size_t)(nBase + ldRow + 32 * p) * DIMC + ldCol];
    }

    for (int k0 = 0; k0 < DIMC; k0 += 32) {
        __syncthreads();
#pragma unroll
        for (int p = 0; p < 4; p++) {
            float4 ta;
            ta.x = to_tf32(ra[p].x); ta.y = to_tf32(ra[p].y);
            ta.z = to_tf32(ra[p].z); ta.w = to_tf32(ra[p].w);
            *(float4*)&As[ldRow + 32 * p][ldCol] = ta;
            float4 tb;
            tb.x = to_tf32(rb[p].x); tb.y = to_tf32(rb[p].y);
            tb.z = to_tf32(rb[p].z); tb.w = to_tf32(rb[p].w);
            *(float4*)&Bs[ldRow + 32 * p][ldCol] = tb;
        }
        __syncthreads();

        if (k0 + 32 < DIMC) {
            const int kn = k0 + 32;
#pragma unroll
            for (int p = 0; p < 4; p++) {
                ra[p] = *(const float4*)&A[(size_t)(mBase + ldRow + 32 * p) * DIMC + kn + ldCol];
                rb[p] = *(const float4*)&W[(size_t)(nBase + ldRow + 32 * p) * DIMC + kn + ldCol];
            }
        }

#pragma unroll
        for (int kk = 0; kk < 32; kk += 8) {
            uint32_t a[4][4];
#pragma unroll
            for (int mi = 0; mi < 4; mi++) {
                const int r = wm * 64 + mi * 16 + (lane >> 2);
                const int col = kk + (lane & 3);
                a[mi][0] = fbits(As[r][col]);
                a[mi][1] = fbits(As[r + 8][col]);
                a[mi][2] = fbits(As[r][col + 4]);
                a[mi][3] = fbits(As[r + 8][col + 4]);
            }
#pragma unroll
            for (int nf = 0; nf < 4; nf++) {
                const int n = wn * 32 + nf * 8 + (lane >> 2);
                const int col = kk + (lane & 3);
                const uint32_t b0 = fbits(Bs[n][col]);
                const uint32_t b1 = fbits(Bs[n][col + 4]);
#pragma unroll
                for (int mi = 0; mi < 4; mi++) mma_tf32(c[mi][nf], a[mi], b0, b1);
            }
        }
    }

#pragma unroll
    for (int mi = 0; mi < 4; mi++) {
        const int gm = mBase + wm * 64 + mi * 16 + (lane >> 2);
        const int b = gm >> 11;
        const int n = gm & 2047;
#pragma unroll
        for (int nf = 0; nf < 4; nf++) {
            const int gn = nBase + wn * 32 + nf * 8 + ((lane & 3) << 1);
            const int h = gn >> 6;
            const int j = gn & 63;
            const size_t base = (((size_t)(b * 16 + h) * SEQ) + n) * 64 + j;
            *(float2*)&Out[base] =
                make_float2(to_tf32(c[mi][nf][0] * scale), to_tf32(c[mi][nf][1] * scale));
            *(float2*)&Out[base + 8 * 64] =
                make_float2(to_tf32(c[mi][nf][2] * scale), to_tf32(c[mi][nf][3] * scale));
        }
    }
}

// Flash attention: CTA = 64 query rows for one (b,h); KV tile = 32,
// cp.async double-buffered K/V, Q fragments register-resident.
// V stored with even-first row permutation within each 8-row group so the
// S C-fragment feeds the PV MMA as an A-fragment with NO shuffles.
__global__ void __launch_bounds__(128, 4) attn(const float* __restrict__ Q,
                                               const float* __restrict__ K,
                                               const float* __restrict__ V,
                                               float* __restrict__ Out) {
    // Layout (floats): Kbuf0[32][68] @0, Kbuf1 @2176, Vbuf0[32][72] @4352, Vbuf1 @6656.
    // Q staging (64x68 = 4352 floats) aliases Kbuf0+Kbuf1 during the prologue.
    __shared__ float sm[2 * 32 * 68 + 2 * 32 * 72];
    float (*Qs)[68] = (float (*)[68])sm;

    const int tid = threadIdx.x;
    const int lane = tid & 31;
    const int warp = tid >> 5;
    const int bh = blockIdx.y;
    const int qBase = blockIdx.x * 64;
    const float* Qg = Q + (size_t)bh * SEQ * 64;
    const float* Kg = K + (size_t)bh * SEQ * 64;
    const float* Vg = V + (size_t)bh * SEQ * 64;

    // --- Prologue: stage Q tile, pull fragments into registers ---
    {
        const int r = tid >> 4;
        const int cc = (tid & 15) << 2;
#pragma unroll
        for (int p = 0; p < 8; p++)
            *(float4*)&Qs[r + 8 * p][cc] =
                *(const float4*)&Qg[(size_t)(qBase + r + 8 * p) * 64 + cc];
    }
    __syncthreads();

    uint32_t qa[8][4];
    {
        const int r = warp * 16 + (lane >> 2);
        const int c0 = lane & 3;
#pragma unroll
        for (int kk = 0; kk < 8; kk++) {
            const int col = kk * 8 + c0;
            qa[kk][0] = fbits(Qs[r][col]);
            qa[kk][1] = fbits(Qs[r + 8][col]);
            qa[kk][2] = fbits(Qs[r][col + 4]);
            qa[kk][3] = fbits(Qs[r + 8][col + 4]);
        }
    }
    __syncthreads();   // Q staging region is about to be overwritten by K buffers

    // cp.async addressing: 512 16B-chunks per tile, 4 per thread.
    // K rows stored as-is; V rows permuted within each 8-group: even rows to
    // slots 0..3, odd rows to slots 4..7 (p(r) = (r>>1) + ((r&1)<<2)).
    const int chRow = tid >> 4;            // rows 0..7 (+8 per i)
    const int chCol = (tid & 15) << 2;     // float col 0..60
    const int vRow = (chRow >> 1) + ((chRow & 1) << 2);
    const uint32_t kDst0 = smem_u32(&sm[0]) + (uint32_t)(chRow * 68 + chCol) * 4u;
    const uint32_t vDst0 = smem_u32(&sm[4352]) + (uint32_t)(vRow * 72 + chCol) * 4u;

    auto issue_tile = [&](int t) {
        const int buf = t & 1;
        const int kvBase = t * 32;
        const uint32_t kD = kDst0 + buf * (2176 * 4);
        const uint32_t vD = vDst0 + buf * (2304 * 4);
#pragma unroll
        for (int i = 0; i < 4; i++) {
            const int row = chRow + 8 * i;
            cp16(kD + i * (8 * 68 * 4), &Kg[(size_t)(kvBase + row) * 64 + chCol]);
            cp16(vD + i * (8 * 72 * 4), &Vg[(size_t)(kvBase + row) * 64 + chCol]);
        }
        cp_commit();
    };

    constexpr int T = SEQ / 32;
    issue_tile(0);
    issue_tile(1);

    float m0 = -1e30f, m1 = -1e30f, l0 = 0.f, l1 = 0.f;
    float o[8][4];
#pragma unroll
    for (int nf = 0; nf < 8; nf++)
#pragma unroll
        for (int k = 0; k < 4; k++) o[nf][k] = 0.f;

    for (int t = 0; t < T; t++) {
        if (t < T - 1) cp_wait<1>(); else cp_wait<0>();
        __syncthreads();

        const int buf = t & 1;
        const float(*Ks)[68] = (const float(*)[68])&sm[buf * 2176];
        const float(*Vs)[72] = (const float(*)[72])&sm[4352 + buf * 2304];

        // S = Q K^T  (Q pre-scaled by 1/8 at projection)
        float s[4][4];
#pragma unroll
        for (int nf = 0; nf < 4; nf++)
#pragma unroll
            for (int k = 0; k < 4; k++) s[nf][k] = 0.f;

#pragma unroll
        for (int kk = 0; kk < 8; kk++) {
            const int col = kk * 8 + (lane & 3);
#pragma unroll
            for (int nf = 0; nf < 4; nf++) {
                const int n = nf * 8 + (lane >> 2);
                const uint32_t b0 = fbits(Ks[n][col]);
                const uint32_t b1 = fbits(Ks[n][col + 4]);
                mma_tf32(s[nf], qa[kk], b0, b1);
            }
        }

        // online softmax (rows r0, r1=r0+8 per lane)
        float tm0 = -1e30f, tm1 = -1e30f;
#pragma unroll
        for (int nf = 0; nf < 4; nf++) {
            tm0 = fmaxf(tm0, fmaxf(s[nf][0], s[nf][1]));
            tm1 = fmaxf(tm1, fmaxf(s[nf][2], s[nf][3]));
        }
        tm0 = fmaxf(tm0, __shfl_xor_sync(FULL_MASK, tm0, 1));
        tm0 = fmaxf(tm0, __shfl_xor_sync(FULL_MASK, tm0, 2));
        tm1 = fmaxf(tm1, __shfl_xor_sync(FULL_MASK, tm1, 1));
        tm1 = fmaxf(tm1, __shfl_xor_sync(FULL_MASK, tm1, 2));
        const float nm0 = fmaxf(m0, tm0);
        const float nm1 = fmaxf(m1, tm1);
        const float al0 = __expf(m0 - nm0);
        const float al1 = __expf(m1 - nm1);
        float rs0 = 0.f, rs1 = 0.f;
#pragma unroll
        for (int nf = 0; nf < 4; nf++) {
            s[nf][0] = __expf(s[nf][0] - nm0);
            s[nf][1] = __expf(s[nf][1] - nm0);
            s[nf][2] = __expf(s[nf][2] - nm1);
            s[nf][3] = __expf(s[nf][3] - nm1);
            rs0 += s[nf][0] + s[nf][1];
            rs1 += s[nf][2] + s[nf][3];
        }
        rs0 += __shfl_xor_sync(FULL_MASK, rs0, 1);
        rs0 += __shfl_xor_sync(FULL_MASK, rs0, 2);
        rs1 += __shfl_xor_sync(FULL_MASK, rs1, 1);
        rs1 += __shfl_xor_sync(FULL_MASK, rs1, 2);
        l0 = l0 * al0 + rs0;
        l1 = l1 * al1 + rs1;
        m0 = nm0; m1 = nm1;
#pragma unroll
        for (int nf = 0; nf < 8; nf++) {
            o[nf][0] *= al0; o[nf][1] *= al0;
            o[nf][2] *= al1; o[nf][3] *= al1;
        }

        // O += P V, shuffle-free: C-frag (P[r,2q], P[r,2q+1], P[r+8,2q], P[r+8,2q+1])
        // is exactly the A-frag {a0,a1,a2,a3} = {P'[r,q], P'[r+8,q], P'[r,q+4], P'[r+8,q+4]}
        // under the even-first V row permutation applied at store time.
#pragma unroll
        for (int kt = 0; kt < 4; kt++) {
            uint32_t a[4];
            a[0] = fbits(to_tf32(s[kt][0]));
            a[1] = fbits(to_tf32(s[kt][2]));
            a[2] = fbits(to_tf32(s[kt][1]));
            a[3] = fbits(to_tf32(s[kt][3]));
#pragma unroll
            for (int nf = 0; nf < 8; nf++) {
                const int n = nf * 8 + (lane >> 2);
                const uint32_t b0 = fbits(Vs[kt * 8 + (lane & 3)][n]);
                const uint32_t b1 = fbits(Vs[kt * 8 + (lane & 3) + 4][n]);
                mma_tf32(o[nf], a, b0, b1);
            }
        }

        __syncthreads();   // all warps done with buf before it is refilled
        if (t + 2 < T) issue_tile(t + 2);
    }

    // epilogue: Out[b, q, h*64 + j] = O / l
    const float inv0 = 1.f / l0;
    const float inv1 = 1.f / l1;
    const int b = bh >> 4;
    const int h = bh & 15;
    const int r0 = qBase + warp * 16 + (lane >> 2);
#pragma unroll
    for (int nf = 0; nf < 8; nf++) {
        const int col = h * 64 + nf * 8 + ((lane & 3) << 1);
        const size_t i0 = ((size_t)b * SEQ + r0) * DIMC + col;
        *(float2*)&Out[i0] = make_float2(o[nf][0] * inv0, o[nf][1] * inv0);
        *(float2*)&Out[i0 + (size_t)8 * DIMC] = make_float2(o[nf][2] * inv1, o[nf][3] * inv1);
    }
}

extern "C" void kernel_launch(void* const* d_in, const int* in_sizes, int n_in,
                              void* d_out, int out_size) {
    const float* x  = (const float*)d_in[0];
    const float* kv = (const float*)d_in[1];
    const float* Wq = (const float*)d_in[2];
    const float* Wk = (const float*)d_in[3];
    const float* Wv = (const float*)d_in[4];
    float* out = (float*)d_out;

    float *Qg, *Kg, *Vg;
    cudaGetSymbolAddress((void**)&Qg, g_Q);
    cudaGetSymbolAddress((void**)&Kg, g_K);
    cudaGetSymbolAddress((void**)&Vg, g_V);

    dim3 gg(DIMC / 128, (4 * SEQ) / 128);   // (8, 64)
    proj_gemm<<<gg, 256>>>(x,  Wq, Qg, 0.125f);  // fold 1/sqrt(64) into Q
    proj_gemm<<<gg, 256>>>(kv, Wk, Kg, 1.0f);
    proj_gemm<<<gg, 256>>>(kv, Wv, Vg, 1.0f);
    attn<<<dim3(SEQ / 64, 64), 128>>>(Qg, Kg, Vg, out);
}

// round 7
// speedup vs baseline: 1.2507x; 1.0523x over previous
#include <cuda_runtime.h>
#include <cstdint>

#define FULL_MASK 0xffffffffu

// Problem constants: B=4, N=2048, DIM=1024, H=16, d=64
static constexpr int SEQ = 2048;
static constexpr int DIMC = 1024;

// Scratch for projected Q/K/V in head-split layout [B,H,N,64].
// Values are tf32-rounded fp32 (Q additionally pre-scaled by 1/8).
__device__ float g_Q[4 * 2048 * 1024];
__device__ float g_K[4 * 2048 * 1024];
__device__ float g_V[4 * 2048 * 1024];

static __device__ __forceinline__ float to_tf32(float x) {
    uint32_t u;
    asm("cvt.rna.tf32.f32 %0, %1;" : "=r"(u) : "f"(x));
    return __uint_as_float(u);
}
static __device__ __forceinline__ uint32_t fbits(float x) { return __float_as_uint(x); }

static __device__ __forceinline__ void mma_tf32(float c[4], const uint32_t a[4],
                                                uint32_t b0, uint32_t b1) {
    asm("mma.sync.aligned.m16n8k8.row.col.f32.tf32.tf32.f32 "
        "{%0,%1,%2,%3},{%4,%5,%6,%7},{%8,%9},{%0,%1,%2,%3};"
        : "+f"(c[0]), "+f"(c[1]), "+f"(c[2]), "+f"(c[3])
        : "r"(a[0]), "r"(a[1]), "r"(a[2]), "r"(a[3]), "r"(b0), "r"(b1));
}

static __device__ __forceinline__ uint32_t smem_u32(const void* p) {
    return (uint32_t)__cvta_generic_to_shared(p);
}
static __device__ __forceinline__ void cp16(uint32_t dst, const void* src) {
    asm volatile("cp.async.cg.shared.global [%0], [%1], 16;" :: "r"(dst), "l"(src));
}
static __device__ __forceinline__ void cp_commit() {
    asm volatile("cp.async.commit_group;");
}
template <int N>
static __device__ __forceinline__ void cp_wait() {
    asm volatile("cp.async.wait_group %0;" :: "n"(N));
}

// C[m][n] = sum_k A[m][k] * W[n][k]; stores to_tf32(C * scale), head-split layout.
__global__ void __launch_bounds__(256) proj_gemm(const float* __restrict__ A,
                                                 const float* __restrict__ W,
                                                 float* __restrict__ Out,
                                                 float scale) {
    __shared__ float As[128][36];
    __shared__ float Bs[128][36];
    const int tid = threadIdx.x;
    const int lane = tid & 31;
    const int warp = tid >> 5;
    const int wm = warp & 1;
    const int wn = warp >> 1;
    const int mBase = blockIdx.y * 128;
    const int nBase = blockIdx.x * 128;

    float c[4][4][4];
#pragma unroll
    for (int i = 0; i < 4; i++)
#pragma unroll
        for (int j = 0; j < 4; j++)
#pragma unroll
            for (int k = 0; k < 4; k++) c[i][j][k] = 0.f;

    const int ldRow = tid >> 3;
    const int ldCol = (tid & 7) << 2;

    float4 ra[4], rb[4];
#pragma unroll
    for (int p = 0; p < 4; p++) {
        ra[p] = *(const float4*)&A[(size_t)(mBase + ldRow + 32 * p) * DIMC + ldCol];
        rb[p] = *(const float4*)&W[(size_t)(nBase + ldRow + 32 * p) * DIMC + ldCol];
    }

    for (int k0 = 0; k0 < DIMC; k0 += 32) {
        __syncthreads();
#pragma unroll
        for (int p = 0; p < 4; p++) {
            float4 ta;
            ta.x = to_tf32(ra[p].x); ta.y = to_tf32(ra[p].y);
            ta.z = to_tf32(ra[p].z); ta.w = to_tf32(ra[p].w);
            *(float4*)&As[ldRow + 32 * p][ldCol] = ta;
            float4 tb;
            tb.x = to_tf32(rb[p].x); tb.y = to_tf32(rb[p].y);
            tb.z = to_tf32(rb[p].z); tb.w = to_tf32(rb[p].w);
            *(float4*)&Bs[ldRow + 32 * p][ldCol] = tb;
        }
        __syncthreads();

        if (k0 + 32 < DIMC) {
            const int kn = k0 + 32;
#pragma unroll
            for (int p = 0; p < 4; p++) {
                ra[p] = *(const float4*)&A[(size_t)(mBase + ldRow + 32 * p) * DIMC + kn + ldCol];
                rb[p] = *(const float4*)&W[(size_t)(nBase + ldRow + 32 * p) * DIMC + kn + ldCol];
            }
        }

#pragma unroll
        for (int kk = 0; kk < 32; kk += 8) {
            uint32_t a[4][4];
#pragma unroll
            for (int mi = 0; mi < 4; mi++) {
                const int r = wm * 64 + mi * 16 + (lane >> 2);
                const int col = kk + (lane & 3);
                a[mi][0] = fbits(As[r][col]);
                a[mi][1] = fbits(As[r + 8][col]);
                a[mi][2] = fbits(As[r][col + 4]);
                a[mi][3] = fbits(As[r + 8][col + 4]);
            }
#pragma unroll
            for (int nf = 0; nf < 4; nf++) {
                const int n = wn * 32 + nf * 8 + (lane >> 2);
                const int col = kk + (lane & 3);
                const uint32_t b0 = fbits(Bs[n][col]);
                const uint32_t b1 = fbits(Bs[n][col + 4]);
#pragma unroll
                for (int mi = 0; mi < 4; mi++) mma_tf32(c[mi][nf], a[mi], b0, b1);
            }
        }
    }

#pragma unroll
    for (int mi = 0; mi < 4; mi++) {
        const int gm = mBase + wm * 64 + mi * 16 + (lane >> 2);
        const int b = gm >> 11;
        const int n = gm & 2047;
#pragma unroll
        for (int nf = 0; nf < 4; nf++) {
            const int gn = nBase + wn * 32 + nf * 8 + ((lane & 3) << 1);
            const int h = gn >> 6;
            const int j = gn & 63;
            const size_t base = (((size_t)(b * 16 + h) * SEQ) + n) * 64 + j;
            *(float2*)&Out[base] =
                make_float2(to_tf32(c[mi][nf][0] * scale), to_tf32(c[mi][nf][1] * scale));
            *(float2*)&Out[base + 8 * 64] =
                make_float2(to_tf32(c[mi][nf][2] * scale), to_tf32(c[mi][nf][3] * scale));
        }
    }
}

// Flash attention: CTA = 128 query rows for one (b,h); warp m-tile = 32 rows
// (2 m-fragments) so each K/V B-fragment LDS feeds TWO MMAs. KV tile = 32,
// cp.async double-buffered, Q fragments register-resident, V rows permuted
// even-first so the S C-fragment feeds PV as an A-fragment with no shuffles.
__global__ void __launch_bounds__(128, 2) attn(const float* __restrict__ Q,
                                               const float* __restrict__ K,
                                               const float* __restrict__ V,
                                               float* __restrict__ Out) {
    // Layout (floats): Kbuf0[32][68] @0, Kbuf1 @2176, Vbuf0[32][72] @4352, Vbuf1 @6656.
    // Q staging (128x68 = 8704 floats) aliases the K/V buffers during the prologue.
    __shared__ float sm[2 * 32 * 68 + 2 * 32 * 72];   // 8960 floats
    float (*Qs)[68] = (float (*)[68])sm;

    const int tid = threadIdx.x;
    const int lane = tid & 31;
    const int warp = tid >> 5;
    const int bh = blockIdx.y;
    const int qBase = blockIdx.x * 128;
    const float* Qg = Q + (size_t)bh * SEQ * 64;
    const float* Kg = K + (size_t)bh * SEQ * 64;
    const float* Vg = V + (size_t)bh * SEQ * 64;

    // --- Prologue: stage 128 Q rows, pull fragments into registers ---
    {
        const int r = tid >> 4;
        const int cc = (tid & 15) << 2;
#pragma unroll
        for (int p = 0; p < 16; p++)
            *(float4*)&Qs[r + 8 * p][cc] =
                *(const float4*)&Qg[(size_t)(qBase + r + 8 * p) * 64 + cc];
    }
    __syncthreads();

    uint32_t qa[2][8][4];
#pragma unroll
    for (int mi = 0; mi < 2; mi++) {
        const int r = warp * 32 + mi * 16 + (lane >> 2);
        const int c0 = lane & 3;
#pragma unroll
        for (int kk = 0; kk < 8; kk++) {
            const int col = kk * 8 + c0;
            qa[mi][kk][0] = fbits(Qs[r][col]);
            qa[mi][kk][1] = fbits(Qs[r + 8][col]);
            qa[mi][kk][2] = fbits(Qs[r][col + 4]);
            qa[mi][kk][3] = fbits(Qs[r + 8][col + 4]);
        }
    }
    __syncthreads();   // Q staging region is about to be overwritten by K buffers

    // cp.async addressing: K rows as-is; V rows permuted within each 8-group
    // (p(r) = (r>>1) + ((r&1)<<2)) for the shuffle-free PV feed.
    const int chRow = tid >> 4;            // rows 0..7 (+8 per i)
    const int chCol = (tid & 15) << 2;     // float col 0..60
    const int vRow = (chRow >> 1) + ((chRow & 1) << 2);
    const uint32_t kDst0 = smem_u32(&sm[0]) + (uint32_t)(chRow * 68 + chCol) * 4u;
    const uint32_t vDst0 = smem_u32(&sm[4352]) + (uint32_t)(vRow * 72 + chCol) * 4u;

    auto issue_tile = [&](int t) {
        const int buf = t & 1;
        const int kvBase = t * 32;
        const uint32_t kD = kDst0 + buf * (2176 * 4);
        const uint32_t vD = vDst0 + buf * (2304 * 4);
#pragma unroll
        for (int i = 0; i < 4; i++) {
            const int row = chRow + 8 * i;
            cp16(kD + i * (8 * 68 * 4), &Kg[(size_t)(kvBase + row) * 64 + chCol]);
            cp16(vD + i * (8 * 72 * 4), &Vg[(size_t)(kvBase + row) * 64 + chCol]);
        }
        cp_commit();
    };

    constexpr int T = SEQ / 32;
    issue_tile(0);
    issue_tile(1);

    float mx[2][2], ls[2][2];
#pragma unroll
    for (int mi = 0; mi < 2; mi++) {
        mx[mi][0] = -1e30f; mx[mi][1] = -1e30f;
        ls[mi][0] = 0.f;    ls[mi][1] = 0.f;
    }
    float o[2][8][4];
#pragma unroll
    for (int mi = 0; mi < 2; mi++)
#pragma unroll
        for (int nf = 0; nf < 8; nf++)
#pragma unroll
            for (int k = 0; k < 4; k++) o[mi][nf][k] = 0.f;

    for (int t = 0; t < T; t++) {
        if (t < T - 1) cp_wait<1>(); else cp_wait<0>();
        __syncthreads();

        const int buf = t & 1;
        const float(*Ks)[68] = (const float(*)[68])&sm[buf * 2176];
        const float(*Vs)[72] = (const float(*)[72])&sm[4352 + buf * 2304];

        // S = Q K^T  (Q pre-scaled by 1/8 at projection); each B-frag -> 2 MMAs
        float s[2][4][4];
#pragma unroll
        for (int mi = 0; mi < 2; mi++)
#pragma unroll
            for (int nf = 0; nf < 4; nf++)
#pragma unroll
                for (int k = 0; k < 4; k++) s[mi][nf][k] = 0.f;

#pragma unroll
        for (int kk = 0; kk < 8; kk++) {
            const int col = kk * 8 + (lane & 3);
#pragma unroll
            for (int nf = 0; nf < 4; nf++) {
                const int n = nf * 8 + (lane >> 2);
                const uint32_t b0 = fbits(Ks[n][col]);
                const uint32_t b1 = fbits(Ks[n][col + 4]);
                mma_tf32(s[0][nf], qa[0][kk], b0, b1);
                mma_tf32(s[1][nf], qa[1][kk], b0, b1);
            }
        }

        // online softmax per m-fragment
#pragma unroll
        for (int mi = 0; mi < 2; mi++) {
            float tm0 = -1e30f, tm1 = -1e30f;
#pragma unroll
            for (int nf = 0; nf < 4; nf++) {
                tm0 = fmaxf(tm0, fmaxf(s[mi][nf][0], s[mi][nf][1]));
                tm1 = fmaxf(tm1, fmaxf(s[mi][nf][2], s[mi][nf][3]));
            }
            tm0 = fmaxf(tm0, __shfl_xor_sync(FULL_MASK, tm0, 1));
            tm0 = fmaxf(tm0, __shfl_xor_sync(FULL_MASK, tm0, 2));
            tm1 = fmaxf(tm1, __shfl_xor_sync(FULL_MASK, tm1, 1));
            tm1 = fmaxf(tm1, __shfl_xor_sync(FULL_MASK, tm1, 2));
            const float nm0 = fmaxf(mx[mi][0], tm0);
            const float nm1 = fmaxf(mx[mi][1], tm1);
            const float al0 = __expf(mx[mi][0] - nm0);
            const float al1 = __expf(mx[mi][1] - nm1);
            float rs0 = 0.f, rs1 = 0.f;
#pragma unroll
            for (int nf = 0; nf < 4; nf++) {
                s[mi][nf][0] = __expf(s[mi][nf][0] - nm0);
                s[mi][nf][1] = __expf(s[mi][nf][1] - nm0);
                s[mi][nf][2] = __expf(s[mi][nf][2] - nm1);
                s[mi][nf][3] = __expf(s[mi][nf][3] - nm1);
                rs0 += s[mi][nf][0] + s[mi][nf][1];
                rs1 += s[mi][nf][2] + s[mi][nf][3];
            }
            rs0 += __shfl_xor_sync(FULL_MASK, rs0, 1);
            rs0 += __shfl_xor_sync(FULL_MASK, rs0, 2);
            rs1 += __shfl_xor_sync(FULL_MASK, rs1, 1);
            rs1 += __shfl_xor_sync(FULL_MASK, rs1, 2);
            ls[mi][0] = ls[mi][0] * al0 + rs0;
            ls[mi][1] = ls[mi][1] * al1 + rs1;
            mx[mi][0] = nm0; mx[mi][1] = nm1;
#pragma unroll
            for (int nf = 0; nf < 8; nf++) {
                o[mi][nf][0] *= al0; o[mi][nf][1] *= al0;
                o[mi][nf][2] *= al1; o[mi][nf][3] *= al1;
            }
        }

        // O += P V, shuffle-free via the even-first V row permutation.
        // Each V B-frag feeds 2 MMAs (one per m-fragment).
#pragma unroll
        for (int kt = 0; kt < 4; kt++) {
            uint32_t a0[4], a1[4];
            a0[0] = fbits(to_tf32(s[0][kt][0]));
            a0[1] = fbits(to_tf32(s[0][kt][2]));
            a0[2] = fbits(to_tf32(s[0][kt][1]));
            a0[3] = fbits(to_tf32(s[0][kt][3]));
            a1[0] = fbits(to_tf32(s[1][kt][0]));
            a1[1] = fbits(to_tf32(s[1][kt][2]));
            a1[2] = fbits(to_tf32(s[1][kt][1]));
            a1[3] = fbits(to_tf32(s[1][kt][3]));
#pragma unroll
            for (int nf = 0; nf < 8; nf++) {
                const int n = nf * 8 + (lane >> 2);
                const uint32_t b0 = fbits(Vs[kt * 8 + (lane & 3)][n]);
                const uint32_t b1 = fbits(Vs[kt * 8 + (lane & 3) + 4][n]);
                mma_tf32(o[0][nf], a0, b0, b1);
                mma_tf32(o[1][nf], a1, b0, b1);
            }
        }

        __syncthreads();   // all warps done with buf before it is refilled
        if (t + 2 < T) issue_tile(t + 2);
    }

    // epilogue: Out[b, q, h*64 + j] = O / l
    const int b = bh >> 4;
    const int h = bh & 15;
#pragma unroll
    for (int mi = 0; mi < 2; mi++) {
        const float inv0 = 1.f / ls[mi][0];
        const float inv1 = 1.f / ls[mi][1];
        const int r0 = qBase + warp * 32 + mi * 16 + (lane >> 2);
#pragma unroll
        for (int nf = 0; nf < 8; nf++) {
            const int col = h * 64 + nf * 8 + ((lane & 3) << 1);
            const size_t i0 = ((size_t)b * SEQ + r0) * DIMC + col;
            *(float2*)&Out[i0] =
                make_float2(o[mi][nf][0] * inv0, o[mi][nf][1] * inv0);
            *(float2*)&Out[i0 + (size_t)8 * DIMC] =
                make_float2(o[mi][nf][2] * inv1, o[mi][nf][3] * inv1);
        }
    }
}

extern "C" void kernel_launch(void* const* d_in, const int* in_sizes, int n_in,
                              void* d_out, int out_size) {
    const float* x  = (const float*)d_in[0];
    const float* kv = (const float*)d_in[1];
    const float* Wq = (const float*)d_in[2];
    const float* Wk = (const float*)d_in[3];
    const float* Wv = (const float*)d_in[4];
    float* out = (float*)d_out;

    float *Qg, *Kg, *Vg;
    cudaGetSymbolAddress((void**)&Qg, g_Q);
    cudaGetSymbolAddress((void**)&Kg, g_K);
    cudaGetSymbolAddress((void**)&Vg, g_V);

    dim3 gg(DIMC / 128, (4 * SEQ) / 128);   // (8, 64)
    proj_gemm<<<gg, 256>>>(x,  Wq, Qg, 0.125f);  // fold 1/sqrt(64) into Q
    proj_gemm<<<gg, 256>>>(kv, Wk, Kg, 1.0f);
    proj_gemm<<<gg, 256>>>(kv, Wv, Vg, 1.0f);
    attn<<<dim3(SEQ / 128, 64), 128>>>(Qg, Kg, Vg, out);
}